// round 14
// baseline (speedup 1.0000x reference)
#include <cuda_runtime.h>
#include <cuda_fp16.h>
#include <math.h>
#include <stdint.h>

// Problem constants
#define Bc 4
#define Nc 8192
#define Ec 128
#define Hc 4
#define Dc 32
#define PADc 16
#define Wc 33
#define BHc 16
#define Mc (Bc * Nc)   // 32768 rows

// Scratch (device globals: no allocation allowed in kernel_launch)
__device__ float g_Q[(size_t)BHc * Nc * Dc];     // (B,H,N,D)
__device__ float g_K[(size_t)BHc * Nc * Dc];
__device__ float g_V[(size_t)BHc * Nc * Dc];
__device__ float g_ctx[(size_t)Mc * Ec];          // (B,N,E)

__device__ __forceinline__ uint32_t pack_h2(float a, float b) {
    __half2 h = __floats2half2_rn(a, b);   // a -> low half (first in memory)
    return *(uint32_t*)&h;
}

// split x = hi + lo with both fp16; packs two lanes at once
__device__ __forceinline__ void split2(float x0, float x1, uint32_t& hi, uint32_t& lo) {
    __half h0 = __float2half_rn(x0), h1 = __float2half_rn(x1);
    __half l0 = __float2half_rn(x0 - __half2float(h0));
    __half l1 = __float2half_rn(x1 - __half2float(h1));
    __half2 H = __halves2half2(h0, h1);
    __half2 L = __halves2half2(l0, l1);
    hi = *(uint32_t*)&H;
    lo = *(uint32_t*)&L;
}

__device__ __forceinline__ void mma_f16(
    float& c0, float& c1, float& c2, float& c3,
    uint32_t a0, uint32_t a1, uint32_t a2, uint32_t a3,
    uint32_t b0, uint32_t b1)
{
    asm volatile(
        "mma.sync.aligned.m16n8k16.row.col.f32.f16.f16.f32 "
        "{%0,%1,%2,%3}, {%4,%5,%6,%7}, {%8,%9}, {%0,%1,%2,%3};\n"
        : "+f"(c0), "+f"(c1), "+f"(c2), "+f"(c3)
        : "r"(a0), "r"(a1), "r"(a2), "r"(a3), "r"(b0), "r"(b1));
}

__device__ __forceinline__ void ldsm_x4(
    uint32_t& r0, uint32_t& r1, uint32_t& r2, uint32_t& r3, uint32_t saddr)
{
    asm volatile("ldmatrix.sync.aligned.m8n8.x4.shared.b16 {%0,%1,%2,%3}, [%4];"
                 : "=r"(r0), "=r"(r1), "=r"(r2), "=r"(r3) : "r"(saddr));
}

// ---------------------------------------------------------------------------
// fp16 MMA GEMM core (R13, proven): C(128x128) = A @ B^T (+bias)
// 256 threads = 8 warps; warp grid 4(M) x 2(N); warp tile 32x64.
// ---------------------------------------------------------------------------
#define HSTR 136                       // halves per smem row
#define HROW (HSTR * 2)                // bytes per smem row (272)
#define HB_OFF (128 * HROW)            // B tile offset (34816 B)
#define H_TOTAL (2 * 128 * HROW)       // 69632 B

#define GEMM_F16_BODY(A_PTR, B_PTR, EPILOGUE)                                   \
    extern __shared__ __align__(16) char smh[];                                 \
    const int tid  = threadIdx.x;                                               \
    const int wid  = tid >> 5;                                                  \
    const int lane = tid & 31;                                                  \
    const int wm   = wid >> 1;       /* 0..3 */                                 \
    const int wn   = wid & 1;        /* 0..1 */                                 \
    const int gr   = lane >> 2;      /* 0..7 */                                 \
    const int gc   = lane & 3;       /* 0..3 */                                 \
    const int lm   = lane >> 3;      /* ldmatrix matrix idx 0..3 */             \
    const int lr   = lane & 7;       /* ldmatrix row-in-matrix */               \
    const int m0   = blockIdx.x * 128;                                          \
    _Pragma("unroll")                                                           \
    for (int l = 0; l < 16; l++) {                                              \
        int li = tid + l * 256;        /* 0..4095 */                            \
        int r  = li >> 5;              /* 0..127 */                             \
        int c4 = (li & 31) * 4;        /* 0..124 */                             \
        float4 va = *(const float4*)(A_PTR + (size_t)(m0 + r) * 128 + c4);      \
        uint2 ua;                                                               \
        ua.x = pack_h2(va.x, va.y);                                             \
        ua.y = pack_h2(va.z, va.w);                                             \
        *(uint2*)(smh + (size_t)r * HROW + c4 * 2) = ua;                        \
        float4 vb = *(const float4*)(B_PTR + (size_t)r * 128 + c4);             \
        uint2 ub;                                                               \
        ub.x = pack_h2(vb.x, vb.y);                                             \
        ub.y = pack_h2(vb.z, vb.w);                                             \
        *(uint2*)(smh + HB_OFF + (size_t)r * HROW + c4 * 2) = ub;               \
    }                                                                           \
    __syncthreads();                                                            \
    const uint32_t asB = (uint32_t)__cvta_generic_to_shared(smh);               \
    const uint32_t bsB = asB + HB_OFF;                                          \
    uint32_t aAddr[2], bAddr[4];                                                \
    _Pragma("unroll")                                                           \
    for (int i = 0; i < 2; i++)                                                 \
        aAddr[i] = asB + ((wm * 32 + i * 16 + (lm & 1) * 8 + lr) * HSTR         \
                          + (lm >> 1) * 8) * 2;                                 \
    _Pragma("unroll")                                                           \
    for (int j2 = 0; j2 < 4; j2++)                                              \
        bAddr[j2] = bsB + ((wn * 64 + j2 * 16 + (lm >> 1) * 8 + lr) * HSTR      \
                           + (lm & 1) * 8) * 2;                                 \
    float acc[2][8][4];                                                         \
    _Pragma("unroll")                                                           \
    for (int i = 0; i < 2; i++)                                                 \
        _Pragma("unroll")                                                       \
        for (int j = 0; j < 8; j++)                                             \
            _Pragma("unroll")                                                   \
            for (int e = 0; e < 4; e++) acc[i][j][e] = 0.f;                     \
    _Pragma("unroll")                                                           \
    for (int k16 = 0; k16 < 128; k16 += 16) {                                   \
        uint32_t af[2][4];                                                      \
        _Pragma("unroll")                                                       \
        for (int i = 0; i < 2; i++)                                             \
            ldsm_x4(af[i][0], af[i][1], af[i][2], af[i][3],                     \
                    aAddr[i] + k16 * 2);                                        \
        uint32_t bf[8][2];                                                      \
        _Pragma("unroll")                                                       \
        for (int j2 = 0; j2 < 4; j2++)                                          \
            ldsm_x4(bf[2 * j2][0], bf[2 * j2][1],                               \
                    bf[2 * j2 + 1][0], bf[2 * j2 + 1][1],                       \
                    bAddr[j2] + k16 * 2);                                       \
        _Pragma("unroll")                                                       \
        for (int i = 0; i < 2; i++)                                             \
            _Pragma("unroll")                                                   \
            for (int j = 0; j < 8; j++)                                         \
                mma_f16(acc[i][j][0], acc[i][j][1], acc[i][j][2], acc[i][j][3], \
                        af[i][0], af[i][1], af[i][2], af[i][3],                 \
                        bf[j][0], bf[j][1]);                                    \
    }                                                                           \
    EPILOGUE

// ---------------------------------------------------------------------------
// Kernel 1: fused QKV projection -> (B,H,N,D) scatter.  grid = (256, 3)
// ---------------------------------------------------------------------------
__global__ __launch_bounds__(256, 2) void qkv_mma(
    const float* __restrict__ q,
    const float* __restrict__ Wq, const float* __restrict__ bq,
    const float* __restrict__ Wk, const float* __restrict__ bk,
    const float* __restrict__ Wv, const float* __restrict__ bv)
{
    const int which = blockIdx.y;
    const float* __restrict__ Wm = (which == 0) ? Wq : ((which == 1) ? Wk : Wv);
    const float* __restrict__ bm = (which == 0) ? bq : ((which == 1) ? bk : bv);
    float* __restrict__ outp = (which == 0) ? g_Q : ((which == 1) ? g_K : g_V);

    GEMM_F16_BODY(q, Wm,
    {
        _Pragma("unroll")
        for (int i = 0; i < 2; i++) {
            _Pragma("unroll")
            for (int e2 = 0; e2 < 2; e2++) {
                int m = m0 + wm * 32 + i * 16 + gr + e2 * 8;
                int b = m >> 13;
                int n = m & 8191;
                _Pragma("unroll")
                for (int j = 0; j < 8; j++) {
                    int col = wn * 64 + j * 8 + gc * 2;
                    int h = col >> 5;
                    int d = col & 31;
                    float2 v;
                    v.x = acc[i][j][e2 * 2 + 0] + bm[col];
                    v.y = acc[i][j][e2 * 2 + 1] + bm[col + 1];
                    *(float2*)(outp + ((size_t)(b * Hc + h) * Nc + n) * Dc + d) = v;
                }
            }
        }
    })
}

// ---------------------------------------------------------------------------
// Kernel 3: output projection. out = ctx @ Wo.T + bo -> d_out (B,N,E)
// ---------------------------------------------------------------------------
__global__ __launch_bounds__(256, 2) void out_mma(
    const float* __restrict__ Wo, const float* __restrict__ bo,
    float* __restrict__ outp)
{
    const float* __restrict__ ctxp = g_ctx;
    GEMM_F16_BODY(ctxp, Wo,
    {
        _Pragma("unroll")
        for (int i = 0; i < 2; i++) {
            _Pragma("unroll")
            for (int e2 = 0; e2 < 2; e2++) {
                int m = m0 + wm * 32 + i * 16 + gr + e2 * 8;
                _Pragma("unroll")
                for (int j = 0; j < 8; j++) {
                    int col = wn * 64 + j * 8 + gc * 2;
                    float2 v;
                    v.x = acc[i][j][e2 * 2 + 0] + bo[col];
                    v.y = acc[i][j][e2 * 2 + 1] + bo[col + 1];
                    *(float2*)(outp + (size_t)m * 128 + col) = v;
                }
            }
        }
    })
}

// ---------------------------------------------------------------------------
// Kernel 2: fp16 warp-independent sliding-window attention.
// Block = 128 queries (4 warps x 32); each warp owns a dense 64-key window.
// QK via split-fp16 (hi+lo staged separately; score = lo*hi + hi*lo + hi*hi,
// error ~2^-22 — exact to fp32 grade). OOB keys zero-padded (score exactly 0,
// matching reference). Band-zero MMAs skipped. PV via plain fp16 (11-bit
// rounding == previous tf32). Probs: fp32 compact staging + coalesced store.
// grid = (N/128, BHc), 128 threads. smem 91648 B.
// ---------------------------------------------------------------------------
#define AQS 40     // Q/K stride in halves (80 B/row; 20-word pattern, conflict-free)
#define AVS 168    // Vt stride in halves (336 B/row; 84-word pattern)
#define APS 72     // Ph stride in halves (144 B/row; 36-word pattern)
#define ASS 68     // Sw stride in floats (68 mod 32 = 4)

// byte offsets in dynamic smem
#define AO_QHI 0
#define AO_QLO 10240
#define AO_KHI 20480
#define AO_KLO 33280
#define AO_VTH 46080
#define AO_SW  56832
#define AO_PH  20480   // overlays K (dead after QK; guarded by __syncthreads)
#define AO_PC  0       // overlays Q (dead after QK)
#define A_TOTAL 91648

__global__ __launch_bounds__(128) void attn_f16(float* __restrict__ probs_out)
{
    extern __shared__ __align__(16) char sma[];
    __half* Qhi = (__half*)(sma + AO_QHI);
    __half* Qlo = (__half*)(sma + AO_QLO);
    __half* Khi = (__half*)(sma + AO_KHI);
    __half* Klo = (__half*)(sma + AO_KLO);
    __half* Vth = (__half*)(sma + AO_VTH);
    float*  Sw0 = (float*)(sma + AO_SW);

    const int tile = blockIdx.x;
    const int bh   = blockIdx.y;
    const int tid  = threadIdx.x;
    const int wid  = tid >> 5;
    const int lane = tid & 31;
    const int gr   = lane >> 2;
    const int gc   = lane & 3;
    const int lm   = lane >> 3;
    const int lr   = lane & 7;
    const int n0   = tile * 128;
    const int g0   = n0 - PADc;

    const float* __restrict__ Qg = g_Q + (size_t)bh * Nc * Dc;
    const float* __restrict__ Kg = g_K + (size_t)bh * Nc * Dc;
    const float* __restrict__ Vg = g_V + (size_t)bh * Nc * Dc;

    // Stage Q (128x32) split hi/lo
#pragma unroll
    for (int l = 0; l < 8; l++) {
        int idx = tid + l * 128;
        int r   = idx >> 3;
        int c4  = (idx & 7) * 4;
        float4 v = *(const float4*)(Qg + (size_t)(n0 + r) * 32 + c4);
        uint2 uh, ul;
        split2(v.x, v.y, uh.x, ul.x);
        split2(v.z, v.w, uh.y, ul.y);
        *(uint2*)(Qhi + r * AQS + c4) = uh;
        *(uint2*)(Qlo + r * AQS + c4) = ul;
    }
    // Stage K (160x32, zero OOB) split hi/lo, and V transposed fp16
#pragma unroll
    for (int l = 0; l < 10; l++) {
        int idx = tid + l * 128;
        int r   = idx >> 3;                 // 0..159
        int c4  = (idx & 7) * 4;
        int grow = g0 + r;
        float4 kv = make_float4(0.f, 0.f, 0.f, 0.f);
        float4 vv = make_float4(0.f, 0.f, 0.f, 0.f);
        if (grow >= 0 && grow < Nc) {
            kv = *(const float4*)(Kg + (size_t)grow * 32 + c4);
            vv = *(const float4*)(Vg + (size_t)grow * 32 + c4);
        }
        uint2 uh, ul;
        split2(kv.x, kv.y, uh.x, ul.x);
        split2(kv.z, kv.w, uh.y, ul.y);
        *(uint2*)(Khi + r * AQS + c4) = uh;
        *(uint2*)(Klo + r * AQS + c4) = ul;
        Vth[(c4 + 0) * AVS + r] = __float2half_rn(vv.x);
        Vth[(c4 + 1) * AVS + r] = __float2half_rn(vv.y);
        Vth[(c4 + 2) * AVS + r] = __float2half_rn(vv.z);
        Vth[(c4 + 3) * AVS + r] = __float2half_rn(vv.w);
    }
    __syncthreads();

    float* Sw = Sw0 + wid * (32 * ASS);
    const int woff = wid * 32;              // warp's key-window offset

    // Fragment addresses (byte) for split-fp16 QK
    const uint32_t qhiB = (uint32_t)__cvta_generic_to_shared(Qhi);
    const uint32_t qloB = (uint32_t)__cvta_generic_to_shared(Qlo);
    const uint32_t khiB = (uint32_t)__cvta_generic_to_shared(Khi);
    const uint32_t kloB = (uint32_t)__cvta_generic_to_shared(Klo);
    uint32_t aHi[2], aLo[2], bHiA[4], bLoA[4];
#pragma unroll
    for (int i = 0; i < 2; i++) {
        uint32_t off = ((woff + i * 16 + (lm & 1) * 8 + lr) * AQS + (lm >> 1) * 8) * 2;
        aHi[i] = qhiB + off;
        aLo[i] = qloB + off;
    }
#pragma unroll
    for (int j2 = 0; j2 < 4; j2++) {
        uint32_t off = ((woff + j2 * 16 + (lm >> 1) * 8 + lr) * AQS + (lm & 1) * 8) * 2;
        bHiA[j2] = khiB + off;
        bLoA[j2] = kloB + off;
    }

    // ---- QK^T: S(32x64) = (Qhi+Qlo)(Khi+Klo)^T, dropping lo*lo ----
    float acc[2][8][4];
#pragma unroll
    for (int i = 0; i < 2; i++)
#pragma unroll
        for (int j = 0; j < 8; j++)
#pragma unroll
            for (int e = 0; e < 4; e++) acc[i][j][e] = 0.f;

#pragma unroll
    for (int ks = 0; ks < 2; ks++) {
        const int kb = ks * 32;   // 16 halves = 32 B per step
        uint32_t ahi[2][4], alo[2][4];
#pragma unroll
        for (int i = 0; i < 2; i++) {
            ldsm_x4(ahi[i][0], ahi[i][1], ahi[i][2], ahi[i][3], aHi[i] + kb);
            ldsm_x4(alo[i][0], alo[i][1], alo[i][2], alo[i][3], aLo[i] + kb);
        }
        uint32_t bhf[8][2], blf[8][2];
#pragma unroll
        for (int j2 = 0; j2 < 4; j2++) {
            ldsm_x4(bhf[2 * j2][0], bhf[2 * j2][1],
                    bhf[2 * j2 + 1][0], bhf[2 * j2 + 1][1], bHiA[j2] + kb);
            ldsm_x4(blf[2 * j2][0], blf[2 * j2][1],
                    blf[2 * j2 + 1][0], blf[2 * j2 + 1][1], bLoA[j2] + kb);
        }
#pragma unroll
        for (int i = 0; i < 2; i++)
#pragma unroll
            for (int j = 0; j < 8; j++) {
                if (i == 0 && j >= 6) continue;   // fully out-of-band
                if (i == 1 && j <= 1) continue;   // fully out-of-band
                mma_f16(acc[i][j][0], acc[i][j][1], acc[i][j][2], acc[i][j][3],
                        alo[i][0], alo[i][1], alo[i][2], alo[i][3], bhf[j][0], bhf[j][1]);
                mma_f16(acc[i][j][0], acc[i][j][1], acc[i][j][2], acc[i][j][3],
                        ahi[i][0], ahi[i][1], ahi[i][2], ahi[i][3], blf[j][0], blf[j][1]);
                mma_f16(acc[i][j][0], acc[i][j][1], acc[i][j][2], acc[i][j][3],
                        ahi[i][0], ahi[i][1], ahi[i][2], ahi[i][3], bhf[j][0], bhf[j][1]);
            }
    }

    // Epilogue: scale in-band (0 <= c-m <= 32), zero out-of-band; Sw fp32 dense
    const float scale = 0.17677669529663687f;   // 1/sqrt(32)
#pragma unroll
    for (int i = 0; i < 2; i++) {
#pragma unroll
        for (int j = 0; j < 8; j++) {
            int c0 = j * 8 + gc * 2;
#pragma unroll
            for (int e2 = 0; e2 < 2; e2++) {
                int m = i * 16 + gr + e2 * 8;
                int w0 = c0 - m;
                float v0 = (w0 >= 0     && w0 <= 32) ? acc[i][j][e2 * 2 + 0] * scale : 0.f;
                float v1 = (w0 + 1 >= 0 && w0 + 1 <= 32) ? acc[i][j][e2 * 2 + 1] * scale : 0.f;
                float2 v; v.x = v0; v.y = v1;
                *(float2*)&Sw[m * ASS + c0] = v;
            }
        }
    }
    // All QK smem reads (Q, K regions) must complete before Pc/Ph overlays.
    __syncthreads();

    __half* Ph = (__half*)(sma + AO_PH) + wid * (32 * APS);
    float*  Pc = (float*)(sma + AO_PC) + wid * (32 * 33);

    // Zero this warp's dense fp16 P buffer (32 x 72 halves = 1152 words)
    {
        uint32_t* Pz = (uint32_t*)Ph;
#pragma unroll
        for (int k = lane; k < 1152; k += 32) Pz[k] = 0u;
    }
    __syncwarp();

    // ---- softmax per query (lane = local query m) ----
    {
        const int m = lane;
        float* row = Sw + m * ASS;
        float sc[33];
#pragma unroll
        for (int w = 0; w < 33; w++) sc[w] = row[m + w];
        float mx = sc[0];
#pragma unroll
        for (int w = 1; w < 33; w++) mx = fmaxf(mx, sc[w]);
        float ssum = 0.f;
#pragma unroll
        for (int w = 0; w < 33; w++) { sc[w] = __expf(sc[w] - mx); ssum += sc[w]; }
        const float rinv = 1.f / ssum;
#pragma unroll
        for (int w = 0; w < 33; w++) {
            float p = sc[w] * rinv;
            Pc[m * 33 + w] = p;
            Ph[m * APS + m + w] = __float2half_rn(p);
        }
    }
    __syncwarp();

    // Warp-coalesced probs store: 32 queries x 33 floats contiguous in gmem.
    {
        float* gp = probs_out + ((size_t)bh * Nc + n0 + wid * 32) * Wc;
        const float4* Ps4 = (const float4*)Pc;
        float4* Gp4 = (float4*)gp;
#pragma unroll
        for (int i = lane; i < 264; i += 32)   // 1056 floats = 264 float4
            Gp4[i] = Ps4[i];
    }

    // ---- ctx = P(32x64) @ V(64x32) via fp16 MMA ----
    // Row block i uses P cols [i*16, i*16+47] -> i=0: k16 in {0,1,2}; i=1: {1,2,3}.
    const uint32_t phB = (uint32_t)__cvta_generic_to_shared(Ph);
    const uint32_t vtB = (uint32_t)__cvta_generic_to_shared(Vth);
    uint32_t aP[2], bV[2];
#pragma unroll
    for (int i = 0; i < 2; i++)
        aP[i] = phB + ((i * 16 + (lm & 1) * 8 + lr) * APS + (lm >> 1) * 8) * 2;
#pragma unroll
    for (int j2 = 0; j2 < 2; j2++)
        bV[j2] = vtB + ((j2 * 16 + (lm >> 1) * 8 + lr) * AVS + woff + (lm & 1) * 8) * 2;

    float acc2[2][4][4];
#pragma unroll
    for (int i = 0; i < 2; i++)
#pragma unroll
        for (int j = 0; j < 4; j++)
#pragma unroll
            for (int e = 0; e < 4; e++) acc2[i][j][e] = 0.f;

#pragma unroll
    for (int k16 = 0; k16 < 4; k16++) {
        const int kb = k16 * 32;   // 16 keys = 32 B
        uint32_t bf[4][2];
#pragma unroll
        for (int j2 = 0; j2 < 2; j2++)
            ldsm_x4(bf[2 * j2][0], bf[2 * j2][1],
                    bf[2 * j2 + 1][0], bf[2 * j2 + 1][1], bV[j2] + kb);
#pragma unroll
        for (int i = 0; i < 2; i++) {
            if (i == 0 && k16 >= 3) continue;   // P cols 48+ zero for rows 0..15
            if (i == 1 && k16 == 0) continue;   // P cols <16 zero for rows 16..31
            uint32_t af[4];
            ldsm_x4(af[0], af[1], af[2], af[3], aP[i] + kb);
#pragma unroll
            for (int j = 0; j < 4; j++)
                mma_f16(acc2[i][j][0], acc2[i][j][1], acc2[i][j][2], acc2[i][j][3],
                        af[0], af[1], af[2], af[3], bf[j][0], bf[j][1]);
        }
    }

    // Epilogue: ctx -> (B,N,E)
    const int b = bh >> 2;
    const int h = bh & 3;
#pragma unroll
    for (int i = 0; i < 2; i++) {
#pragma unroll
        for (int j = 0; j < 4; j++) {
            int d = j * 8 + gc * 2;
#pragma unroll
            for (int e2 = 0; e2 < 2; e2++) {
                int m = i * 16 + gr + e2 * 8;
                float2 v;
                v.x = acc2[i][j][e2 * 2 + 0];
                v.y = acc2[i][j][e2 * 2 + 1];
                *(float2*)(g_ctx + ((size_t)(b * Nc) + n0 + wid * 32 + m) * Ec + h * 32 + d) = v;
            }
        }
    }
}

// ---------------------------------------------------------------------------
extern "C" void kernel_launch(void* const* d_in, const int* in_sizes, int n_in,
                              void* d_out, int out_size)
{
    (void)in_sizes; (void)n_in; (void)out_size;
    const float* q  = (const float*)d_in[0];
    const float* Wq = (const float*)d_in[1];
    const float* bq = (const float*)d_in[2];
    const float* Wk = (const float*)d_in[3];
    const float* bk = (const float*)d_in[4];
    const float* Wv = (const float*)d_in[5];
    const float* bv = (const float*)d_in[6];
    const float* Wo = (const float*)d_in[7];
    const float* bo = (const float*)d_in[8];

    float* outp  = (float*)d_out;                         // (B,N,E)
    float* probs = outp + (size_t)Bc * Nc * Ec;           // (B,H,N,W)

    cudaFuncSetAttribute(attn_f16, cudaFuncAttributeMaxDynamicSharedMemorySize, A_TOTAL);
    cudaFuncSetAttribute(qkv_mma, cudaFuncAttributeMaxDynamicSharedMemorySize, H_TOTAL);
    cudaFuncSetAttribute(out_mma, cudaFuncAttributeMaxDynamicSharedMemorySize, H_TOTAL);

    qkv_mma<<<dim3(Mc / 128, 3), 256, H_TOTAL>>>(q, Wq, bq, Wk, bk, Wv, bv);
    attn_f16<<<dim3(Nc / 128, BHc), 128, A_TOTAL>>>(probs);
    out_mma<<<dim3(Mc / 128, 1), 256, H_TOTAL>>>(Wo, bo, outp);
}